// round 12
// baseline (speedup 1.0000x reference)
#include <cuda_runtime.h>
#include <cuda_fp16.h>

#define N_VOX 400000
#define C 32
#define K_TAPS 27
#define FULL 0xffffffffu

// W smem: fp16, row per (k,cout), pitch 40 halfs = 80B (16B-aligned; row starts
// walk all 8 bank-groups -> conflict-free LDS.128). Validated in R4-R8.
#define W_PITCH_H 40
#define SMEM_W_BYTES (K_TAPS * 32 * W_PITCH_H * 2)          // 69,120 B

// Per-warp accumulator tile: acc[32 voxels][pitch 36 floats].
// Bank of acc[v][lane] = (4v + lane) mod 32 -> conflict-free for fixed v.
#define ACC_PITCH 36
#define WARPS_PER_BLOCK 8
#define SMEM_ACC_BYTES (WARPS_PER_BLOCK * 32 * ACC_PITCH * 4)  // 36,864 B
#define SMEM_TOTAL (SMEM_W_BYTES + SMEM_ACC_BYTES)             // 105,984 B

// Static device scratch (no allocations allowed).
__device__ float g_h[(size_t)N_VOX * C];                    // conv1 output (fp32)

static __device__ __forceinline__ __half2 as_h2(unsigned u) {
    return *reinterpret_cast<__half2*>(&u);
}
static __device__ __forceinline__ unsigned long long pack2(float lo, float hi) {
    unsigned long long u;
    asm("mov.b64 %0, {%1, %2};" : "=l"(u) : "f"(lo), "f"(hi));
    return u;
}
static __device__ __forceinline__ void unpack2(unsigned long long u, float& lo, float& hi) {
    asm("mov.b64 {%0, %1}, %2;" : "=f"(lo), "=f"(hi) : "l"(u));
}
// Packed dual-fp32 FMA (FFMA2) — PTX-only on sm_103a.
static __device__ __forceinline__ unsigned long long
ffma2(unsigned long long a, unsigned long long b, unsigned long long c) {
    unsigned long long d;
    asm("fma.rn.f32x2 %0, %1, %2, %3;" : "=l"(d) : "l"(a), "l"(b), "l"(c));
    return d;
}

// ---------------------------------------------------------------------------
// k-major fused sparse-conv + LayerNorm + activation.
// Warp owns 32 consecutive voxels. Per tap k: coalesced nbr load (native
// [K,N] layout), W[k] column cached in 16 packed f32x2 registers, then only
// active voxels processed: 8 uniform LDG.128 + 16 FFMA2 + smem RMW.
// ---------------------------------------------------------------------------
template <bool RESID>
__global__ void __launch_bounds__(256)
conv_ln_kernel(const float* __restrict__ in,       // [N,32] fp32
               const int*   __restrict__ nbr,      // [27,N]
               const float* __restrict__ W,        // [27,32,32] fp32 (cin-major)
               const float* __restrict__ gamma,
               const float* __restrict__ beta,
               const float* __restrict__ resid,    // fp32 (RESID only)
               float*       __restrict__ out)      // fp32
{
    extern __shared__ unsigned char smem_raw[];
    __half* ws   = reinterpret_cast<__half*>(smem_raw);
    float*  accs = reinterpret_cast<float*>(smem_raw + SMEM_W_BYTES);

    // Preload + convert + transpose: ws[(k*32+cout)*40 + cin] = half(W[k][cin][cout])
    for (int t = threadIdx.x; t < K_TAPS * 1024; t += blockDim.x) {
        const int k = t >> 10, r = t & 1023, cin = r >> 5, cout = r & 31;
        ws[(k * 32 + cout) * W_PITCH_H + cin] = __float2half_rn(W[t]);
    }
    __syncthreads();

    const int lane = threadIdx.x & 31;
    const int wid  = threadIdx.x >> 5;
    float* acc = accs + wid * (32 * ACC_PITCH);

    const int warp_gid   = (blockIdx.x * blockDim.x + threadIdx.x) >> 5;
    const int warp_total = (gridDim.x * blockDim.x) >> 5;
    const float gm = gamma[lane];
    const float bt = beta[lane];
    const int n_chunks = N_VOX / 32;                 // 12500 exactly

    for (int ch = warp_gid; ch < n_chunks; ch += warp_total) {
        const int i0 = ch * 32;

        // Zero this warp's accumulator tile (32 STS, conflict-free).
        #pragma unroll
        for (int v = 0; v < 32; ++v) acc[v * ACC_PITCH + lane] = 0.0f;

        // 1-deep prefetch of the per-k neighbor vector.
        int idx_cur = nbr[0 * N_VOX + i0 + lane];

        #pragma unroll 1
        for (int k = 0; k < K_TAPS; ++k) {
            const int idx_nxt = (k + 1 < K_TAPS) ? nbr[(k + 1) * N_VOX + i0 + lane] : -1;
            unsigned m = __ballot_sync(FULL, idx_cur >= 0);
            if (m) {
                // W[k] column for cout=lane -> 16 packed f32x2 registers.
                const uint4* __restrict__ wr =
                    reinterpret_cast<const uint4*>(ws + (k * 32 + lane) * W_PITCH_H);
                unsigned long long w[16];
                #pragma unroll
                for (int c = 0; c < 4; ++c) {
                    const uint4 u = wr[c];
                    const float2 f0 = __half22float2(as_h2(u.x));
                    const float2 f1 = __half22float2(as_h2(u.y));
                    const float2 f2 = __half22float2(as_h2(u.z));
                    const float2 f3 = __half22float2(as_h2(u.w));
                    w[c * 4 + 0] = pack2(f0.x, f0.y);
                    w[c * 4 + 1] = pack2(f1.x, f1.y);
                    w[c * 4 + 2] = pack2(f2.x, f2.y);
                    w[c * 4 + 3] = pack2(f3.x, f3.y);
                }

                while (m) {
                    const int j = __ffs(m) - 1;
                    m &= m - 1;
                    const int ij = __shfl_sync(FULL, idx_cur, j);

                    const ulonglong2* __restrict__ xr =
                        reinterpret_cast<const ulonglong2*>(in + (size_t)ij * C);
                    ulonglong2 xq[4];
                    #pragma unroll
                    for (int q = 0; q < 4; ++q) xq[q] = xr[q];
                    ulonglong2 xq2[4];
                    #pragma unroll
                    for (int q = 0; q < 4; ++q) xq2[q] = xr[q + 4];

                    unsigned long long p0 = 0ull, p1 = 0ull, p2 = 0ull, p3 = 0ull;
                    p0 = ffma2(xq[0].x,  w[0],  p0);  p1 = ffma2(xq[0].y,  w[1],  p1);
                    p2 = ffma2(xq[1].x,  w[2],  p2);  p3 = ffma2(xq[1].y,  w[3],  p3);
                    p0 = ffma2(xq[2].x,  w[4],  p0);  p1 = ffma2(xq[2].y,  w[5],  p1);
                    p2 = ffma2(xq[3].x,  w[6],  p2);  p3 = ffma2(xq[3].y,  w[7],  p3);
                    p0 = ffma2(xq2[0].x, w[8],  p0);  p1 = ffma2(xq2[0].y, w[9],  p1);
                    p2 = ffma2(xq2[1].x, w[10], p2);  p3 = ffma2(xq2[1].y, w[11], p3);
                    p0 = ffma2(xq2[2].x, w[12], p0);  p1 = ffma2(xq2[2].y, w[13], p1);
                    p2 = ffma2(xq2[3].x, w[14], p2);  p3 = ffma2(xq2[3].y, w[15], p3);

                    float a, b, c2, d2, e, f, g2, h2;
                    unpack2(p0, a, b);  unpack2(p1, c2, d2);
                    unpack2(p2, e, f);  unpack2(p3, g2, h2);
                    const float dot = ((a + b) + (c2 + d2)) + ((e + f) + (g2 + h2));

                    acc[j * ACC_PITCH + lane] += dot;   // same-warp smem RMW
                }
            }
            idx_cur = idx_nxt;
        }

        // LayerNorm + activation for the 32 voxels of this chunk.
        #pragma unroll 1
        for (int v = 0; v < 32; ++v) {
            const float h = acc[v * ACC_PITCH + lane];
            float s = h, s2 = h * h;
            #pragma unroll
            for (int o = 16; o; o >>= 1) {
                s  += __shfl_xor_sync(FULL, s,  o);
                s2 += __shfl_xor_sync(FULL, s2, o);
            }
            const float mu  = s  * 0.03125f;
            const float var = s2 * 0.03125f - mu * mu;
            float y = (h - mu) * rsqrtf(var + 1e-6f) * gm + bt;
            if (RESID) y += resid[(size_t)(i0 + v) * C + lane];
            out[(size_t)(i0 + v) * C + lane] = fmaxf(y, 0.0f);
        }
    }
}

extern "C" void kernel_launch(void* const* d_in, const int* in_sizes, int n_in,
                              void* d_out, int out_size)
{
    const float* x   = (const float*)d_in[0];  // [N, 32]
    const int*   nbr = (const int*)  d_in[1];  // [27, N]
    const float* W1  = (const float*)d_in[2];  // [27, 32, 32]
    const float* g1  = (const float*)d_in[3];
    const float* b1  = (const float*)d_in[4];
    const float* W2  = (const float*)d_in[5];
    const float* g2  = (const float*)d_in[6];
    const float* b2  = (const float*)d_in[7];
    float* out = (float*)d_out;

    float* h_buf = nullptr;
    cudaGetSymbolAddress((void**)&h_buf, g_h);

    cudaFuncSetAttribute(conv_ln_kernel<false>,
                         cudaFuncAttributeMaxDynamicSharedMemorySize, SMEM_TOTAL);
    cudaFuncSetAttribute(conv_ln_kernel<true>,
                         cudaFuncAttributeMaxDynamicSharedMemorySize, SMEM_TOTAL);

    // 296 blocks of 256 threads -> 2 CTAs/SM (2 x 105,984 B smem).
    // Block 1: h = relu(LN(conv(x, W1)))        (fp32 h)
    conv_ln_kernel<false><<<296, 256, SMEM_TOTAL>>>(x, nbr, W1, g1, b1, nullptr, h_buf);
    // Block 2: out = relu(LN(conv(h, W2)) + x)
    conv_ln_kernel<true ><<<296, 256, SMEM_TOTAL>>>(h_buf, nbr, W2, g2, b2, x, out);
}

// round 13
// speedup vs baseline: 1.9276x; 1.9276x over previous
#include <cuda_runtime.h>
#include <cuda_fp16.h>

#define N_VOX 400000
#define C 32
#define K_TAPS 27
#define FULL 0xffffffffu

#define TILE_M 16
#define N_TILES (N_VOX / TILE_M)          // 25000 exactly

// Wt smem: fp16, row per (k,cout), pitch 40 halfs = 80B (16B-aligned, row
// starts walk all 8 bank-granules -> conflict-free ldmatrix).
#define W_PITCH_H 40
#define SMEM_W_H (K_TAPS * 32 * W_PITCH_H)            // 34560 halfs = 69120 B
// Per-warp A staging: 16 rows x pitch 40 halfs = 1280 B.
#define A_PITCH_H 40
#define A_BYTES (TILE_M * A_PITCH_H * 2)              // 1280
#define WARPS_PER_BLOCK 8
#define SMEM_TOTAL (SMEM_W_H * 2 + WARPS_PER_BLOCK * A_BYTES)   // 79,360 B

// Static device scratch (no allocations allowed).
__device__ __half g_x16[(size_t)N_VOX * C];   // x in fp16
__device__ __half g_h16[(size_t)N_VOX * C];   // conv1 output in fp16

static __device__ __forceinline__ unsigned smem_u32(const void* p) {
    return (unsigned)__cvta_generic_to_shared(p);
}

static __device__ __forceinline__ void ldsm_x4(unsigned addr, unsigned& r0,
                                               unsigned& r1, unsigned& r2, unsigned& r3) {
    asm volatile("ldmatrix.sync.aligned.m8n8.x4.shared.b16 {%0,%1,%2,%3}, [%4];"
                 : "=r"(r0), "=r"(r1), "=r"(r2), "=r"(r3) : "r"(addr));
}

static __device__ __forceinline__ void mma16816(float& d0, float& d1, float& d2, float& d3,
                                                unsigned a0, unsigned a1, unsigned a2, unsigned a3,
                                                unsigned b0, unsigned b1) {
    asm volatile("mma.sync.aligned.m16n8k16.row.col.f32.f16.f16.f32 "
                 "{%0,%1,%2,%3}, {%4,%5,%6,%7}, {%8,%9}, {%0,%1,%2,%3};"
                 : "+f"(d0), "+f"(d1), "+f"(d2), "+f"(d3)
                 : "r"(a0), "r"(a1), "r"(a2), "r"(a3), "r"(b0), "r"(b1));
}

// ---------------------------------------------------------------------------
// Prep: convert x fp32 -> fp16 (12.8M elems, float4 in / 8B out per thread-iter).
// ---------------------------------------------------------------------------
__global__ void __launch_bounds__(256)
prep_kernel(const float* __restrict__ x, __half* __restrict__ x16)
{
    const int t = blockIdx.x * blockDim.x + threadIdx.x;      // 3.2M threads
    const float4 v = reinterpret_cast<const float4*>(x)[t];
    __half2 h0 = __floats2half2_rn(v.x, v.y);
    __half2 h1 = __floats2half2_rn(v.z, v.w);
    uint2 o;
    o.x = *reinterpret_cast<unsigned*>(&h0);
    o.y = *reinterpret_cast<unsigned*>(&h1);
    reinterpret_cast<uint2*>(x16)[t] = o;
}

// ---------------------------------------------------------------------------
// Tensor-core fused sparse-conv + LayerNorm + activation.
// Warp owns 16 voxels. Per tap k: coalesced nbr load + ballot (skip empty),
// cooperative gather of active rows into smem A[16x32] fp16 (zeros for
// inactive), then m16n8k16 mma accumulating D[16x32] fp32 in fragments.
// LN on fragments via quad shuffles. RESID picks fp32-out + residual path.
// ---------------------------------------------------------------------------
template <bool RESID>
__global__ void __launch_bounds__(256)
conv_ln_kernel(const __half* __restrict__ in16,    // [N,32] fp16
               const int*    __restrict__ nbr,     // [27,N] native layout
               const float*  __restrict__ W,       // [27,32,32] fp32 (cin-major)
               const float*  __restrict__ gamma,
               const float*  __restrict__ beta,
               const float*  __restrict__ resid,   // fp32 (RESID only)
               __half*       __restrict__ outH,    // !RESID
               float*        __restrict__ outF)    // RESID
{
    extern __shared__ __half smem[];
    __half* wt = smem;                                         // [27*32][40]
    __half* Abuf = smem + SMEM_W_H + (threadIdx.x >> 5) * (A_BYTES / 2);

    // Stage Wt[k][cout][cin] = W[k][cin][cout] as fp16.
    for (int t = threadIdx.x; t < K_TAPS * 1024; t += blockDim.x) {
        const int k = t >> 10, r = t & 1023, cin = r >> 5, cout = r & 31;
        wt[(k * 32 + cout) * W_PITCH_H + cin] = __float2half_rn(W[t]);
    }
    __syncthreads();

    const int lane = threadIdx.x & 31;
    const int rq   = lane >> 2;            // 0..7  (fill row / C-frag row group)
    const int seg  = lane & 3;             // 16B segment within a 64B row
    const int qm   = lane & 3;             // quad position (C-frag col pair)

    // ldmatrix A address: lane -> (row = lane&15, colblock = (lane>>4)*8)
    const unsigned a_base = smem_u32(Abuf) + (unsigned)((lane & 15) * A_PITCH_H + (lane >> 4) * 8) * 2;
    // A fill STS addresses (two instrs: rows 0-7, rows 8-15)
    const unsigned sts0 = smem_u32(Abuf) + (unsigned)(rq * A_PITCH_H + seg * 8) * 2;
    const unsigned sts1 = sts0 + (unsigned)(8 * A_PITCH_H) * 2;

    // B ldmatrix lane mapping: q = lane>>3: nt_sub = q>>1, koff = (q&1)*8
    const int bq = lane >> 3, bj = lane & 7;
    const int b_row_off = (bq >> 1) * 8 + bj;      // n within a 16-wide pair
    const int b_koff = (bq & 1) * 8;

    // gamma/beta for this thread's 8 columns (2 per ntile).
    float2 g2[4], bb2[4];
    #pragma unroll
    for (int nt = 0; nt < 4; ++nt) {
        g2[nt]  = *reinterpret_cast<const float2*>(&gamma[nt * 8 + 2 * qm]);
        bb2[nt] = *reinterpret_cast<const float2*>(&beta [nt * 8 + 2 * qm]);
    }

    const int warp_gid   = (blockIdx.x * blockDim.x + threadIdx.x) >> 5;
    const int warp_total = (gridDim.x * blockDim.x) >> 5;

    for (int tile = warp_gid; tile < N_TILES; tile += warp_total) {
        const int i0 = tile * TILE_M;

        float c[4][4];
        #pragma unroll
        for (int nt = 0; nt < 4; ++nt)
            #pragma unroll
            for (int e = 0; e < 4; ++e) c[nt][e] = 0.0f;

        // Prefetched neighbor indices (lanes 0..15 hold voxel i0+lane).
        int idx_cur = -1;
        if (lane < 16) idx_cur = nbr[(size_t)0 * N_VOX + i0 + lane];

        #pragma unroll 1
        for (int k = 0; k < K_TAPS; ++k) {
            int idx_nxt = -1;
            if (k + 1 < K_TAPS && lane < 16)
                idx_nxt = nbr[(size_t)(k + 1) * N_VOX + i0 + lane];

            const unsigned mask = __ballot_sync(FULL, idx_cur >= 0) & 0xFFFFu;
            if (mask) {
                // --- Fill A[16][32] fp16: rows 0-7 then 8-15, 8 rows/instr. ---
                const int iA = __shfl_sync(FULL, idx_cur, rq);
                const int iB = __shfl_sync(FULL, idx_cur, 8 + rq);
                uint4 vA = make_uint4(0u, 0u, 0u, 0u);
                uint4 vB = make_uint4(0u, 0u, 0u, 0u);
                if (iA >= 0)
                    vA = reinterpret_cast<const uint4*>(in16 + (size_t)iA * C)[seg];
                if (iB >= 0)
                    vB = reinterpret_cast<const uint4*>(in16 + (size_t)iB * C)[seg];
                asm volatile("st.shared.v4.b32 [%0], {%1,%2,%3,%4};" ::
                             "r"(sts0), "r"(vA.x), "r"(vA.y), "r"(vA.z), "r"(vA.w));
                asm volatile("st.shared.v4.b32 [%0], {%1,%2,%3,%4};" ::
                             "r"(sts1), "r"(vB.x), "r"(vB.y), "r"(vB.z), "r"(vB.w));
                __syncwarp();

                const unsigned wbase = smem_u32(wt) + (unsigned)(k * 32) * W_PITCH_H * 2;
                #pragma unroll
                for (int s = 0; s < 2; ++s) {
                    // A fragment for kstep s (cols s*16 .. s*16+15)
                    unsigned a0, a1, a2, a3;
                    ldsm_x4(a_base + (unsigned)(s * 16) * 2, a0, a1, a2, a3);
                    // B fragments for 4 ntiles (two x4 loads, 2 ntiles each)
                    #pragma unroll
                    for (int p = 0; p < 2; ++p) {
                        const unsigned baddr = wbase +
                            (unsigned)((p * 16 + b_row_off) * W_PITCH_H + s * 16 + b_koff) * 2;
                        unsigned b0, b1, b2, b3;
                        ldsm_x4(baddr, b0, b1, b2, b3);
                        mma16816(c[2*p  ][0], c[2*p  ][1], c[2*p  ][2], c[2*p  ][3],
                                 a0, a1, a2, a3, b0, b1);
                        mma16816(c[2*p+1][0], c[2*p+1][1], c[2*p+1][2], c[2*p+1][3],
                                 a0, a1, a2, a3, b2, b3);
                    }
                }
                __syncwarp();   // protect A before next k's fill
            }
            idx_cur = idx_nxt;
        }

        // --- LayerNorm + activation on C fragments. ---
        // Thread holds rows r0=rq, r1=rq+8; cols nt*8 + 2*qm + {0,1}.
        float s0 = 0.f, q0 = 0.f, s1 = 0.f, q1 = 0.f;
        #pragma unroll
        for (int nt = 0; nt < 4; ++nt) {
            s0 += c[nt][0] + c[nt][1];
            q0 += c[nt][0] * c[nt][0] + c[nt][1] * c[nt][1];
            s1 += c[nt][2] + c[nt][3];
            q1 += c[nt][2] * c[nt][2] + c[nt][3] * c[nt][3];
        }
        #pragma unroll
        for (int o = 1; o <= 2; o <<= 1) {
            s0 += __shfl_xor_sync(FULL, s0, o);
            q0 += __shfl_xor_sync(FULL, q0, o);
            s1 += __shfl_xor_sync(FULL, s1, o);
            q1 += __shfl_xor_sync(FULL, q1, o);
        }
        const float mu0 = s0 * 0.03125f, var0 = q0 * 0.03125f - mu0 * mu0;
        const float mu1 = s1 * 0.03125f, var1 = q1 * 0.03125f - mu1 * mu1;
        const float rs0 = rsqrtf(var0 + 1e-6f);
        const float rs1 = rsqrtf(var1 + 1e-6f);

        const int row0 = i0 + rq, row1 = i0 + rq + 8;
        #pragma unroll
        for (int nt = 0; nt < 4; ++nt) {
            const int colb = nt * 8 + 2 * qm;
            float y00 = (c[nt][0] - mu0) * rs0 * g2[nt].x + bb2[nt].x;
            float y01 = (c[nt][1] - mu0) * rs0 * g2[nt].y + bb2[nt].y;
            float y10 = (c[nt][2] - mu1) * rs1 * g2[nt].x + bb2[nt].x;
            float y11 = (c[nt][3] - mu1) * rs1 * g2[nt].y + bb2[nt].y;
            if (RESID) {
                const float2 r0v = *reinterpret_cast<const float2*>(&resid[(size_t)row0 * C + colb]);
                const float2 r1v = *reinterpret_cast<const float2*>(&resid[(size_t)row1 * C + colb]);
                y00 += r0v.x; y01 += r0v.y; y10 += r1v.x; y11 += r1v.y;
                float2 o0 = make_float2(fmaxf(y00, 0.f), fmaxf(y01, 0.f));
                float2 o1 = make_float2(fmaxf(y10, 0.f), fmaxf(y11, 0.f));
                *reinterpret_cast<float2*>(&outF[(size_t)row0 * C + colb]) = o0;
                *reinterpret_cast<float2*>(&outF[(size_t)row1 * C + colb]) = o1;
            } else {
                __half2 h0 = __floats2half2_rn(fmaxf(y00, 0.f), fmaxf(y01, 0.f));
                __half2 h1 = __floats2half2_rn(fmaxf(y10, 0.f), fmaxf(y11, 0.f));
                *reinterpret_cast<__half2*>(&outH[(size_t)row0 * C + colb]) = h0;
                *reinterpret_cast<__half2*>(&outH[(size_t)row1 * C + colb]) = h1;
            }
        }
    }
}

extern "C" void kernel_launch(void* const* d_in, const int* in_sizes, int n_in,
                              void* d_out, int out_size)
{
    const float* x   = (const float*)d_in[0];  // [N, 32]
    const int*   nbr = (const int*)  d_in[1];  // [27, N]
    const float* W1  = (const float*)d_in[2];  // [27, 32, 32]
    const float* g1  = (const float*)d_in[3];
    const float* b1  = (const float*)d_in[4];
    const float* W2  = (const float*)d_in[5];
    const float* g2  = (const float*)d_in[6];
    const float* b2  = (const float*)d_in[7];
    float* out = (float*)d_out;

    __half* x16 = nullptr;
    __half* h16 = nullptr;
    cudaGetSymbolAddress((void**)&x16, g_x16);
    cudaGetSymbolAddress((void**)&h16, g_h16);

    cudaFuncSetAttribute(conv_ln_kernel<false>,
                         cudaFuncAttributeMaxDynamicSharedMemorySize, SMEM_TOTAL);
    cudaFuncSetAttribute(conv_ln_kernel<true>,
                         cudaFuncAttributeMaxDynamicSharedMemorySize, SMEM_TOTAL);

    // 1) x -> fp16   (12.8M elems, 4 per thread)
    prep_kernel<<<(N_VOX * C / 4) / 256, 256>>>(x, x16);

    // 2) Block 1: h16 = relu(LN(conv(x16, W1)))
    conv_ln_kernel<false><<<296, 256, SMEM_TOTAL>>>(x16, nbr, W1, g1, b1,
                                                    nullptr, h16, nullptr);
    // 3) Block 2: out = relu(LN(conv(h16, W2)) + x)
    conv_ln_kernel<true ><<<296, 256, SMEM_TOTAL>>>(h16, nbr, W2, g2, b2,
                                                    x, nullptr, out);
}

// round 15
// speedup vs baseline: 2.1510x; 1.1159x over previous
#include <cuda_runtime.h>
#include <cuda_fp16.h>

#define N_VOX 400000
#define C 32
#define K_TAPS 27
#define FULL 0xffffffffu

#define TILE_M 32
#define N_TILES (N_VOX / TILE_M)              // 12500 exactly

// Wt smem: fp16, row per (k,cout), pitch 40 halfs = 80B (16B-aligned).
#define W_PITCH_H 40
#define SMEM_W_H (K_TAPS * 32 * W_PITCH_H)    // 34560 halfs = 69120 B
// Per-warp A staging: 32 rows x pitch 40 halfs = 2560 B.
#define A_PITCH_H 40
#define A_BYTES (TILE_M * A_PITCH_H * 2)
#define WARPS_PER_BLOCK 8
#define SMEM_TOTAL (SMEM_W_H * 2 + WARPS_PER_BLOCK * A_BYTES)   // 89,600 B

// Static device scratch (no allocations allowed).
__device__ __half g_x16[(size_t)N_VOX * C];   // x in fp16
__device__ __half g_h16[(size_t)N_VOX * C];   // conv1 output in fp16

static __device__ __forceinline__ unsigned smem_u32(const void* p) {
    return (unsigned)__cvta_generic_to_shared(p);
}
static __device__ __forceinline__ void ldsm_x4(unsigned addr, unsigned& r0,
                                               unsigned& r1, unsigned& r2, unsigned& r3) {
    asm volatile("ldmatrix.sync.aligned.m8n8.x4.shared.b16 {%0,%1,%2,%3}, [%4];"
                 : "=r"(r0), "=r"(r1), "=r"(r2), "=r"(r3) : "r"(addr));
}
static __device__ __forceinline__ void mma16816(float& d0, float& d1, float& d2, float& d3,
                                                unsigned a0, unsigned a1, unsigned a2, unsigned a3,
                                                unsigned b0, unsigned b1) {
    asm volatile("mma.sync.aligned.m16n8k16.row.col.f32.f16.f16.f32 "
                 "{%0,%1,%2,%3}, {%4,%5,%6,%7}, {%8,%9}, {%0,%1,%2,%3};"
                 : "+f"(d0), "+f"(d1), "+f"(d2), "+f"(d3)
                 : "r"(a0), "r"(a1), "r"(a2), "r"(a3), "r"(b0), "r"(b1));
}

// ---------------------------------------------------------------------------
// Prep: x fp32 -> fp16, 8 elems per thread.
// ---------------------------------------------------------------------------
__global__ void __launch_bounds__(256)
prep_kernel(const float* __restrict__ x, __half* __restrict__ x16)
{
    const int t = blockIdx.x * blockDim.x + threadIdx.x;      // 1.6M threads
    const float4 v0 = reinterpret_cast<const float4*>(x)[2 * t];
    const float4 v1 = reinterpret_cast<const float4*>(x)[2 * t + 1];
    __half2 h0 = __floats2half2_rn(v0.x, v0.y);
    __half2 h1 = __floats2half2_rn(v0.z, v0.w);
    __half2 h2 = __floats2half2_rn(v1.x, v1.y);
    __half2 h3 = __floats2half2_rn(v1.z, v1.w);
    uint4 o;
    o.x = *reinterpret_cast<unsigned*>(&h0);
    o.y = *reinterpret_cast<unsigned*>(&h1);
    o.z = *reinterpret_cast<unsigned*>(&h2);
    o.w = *reinterpret_cast<unsigned*>(&h3);
    reinterpret_cast<uint4*>(x16)[t] = o;
}

// ---------------------------------------------------------------------------
// Tensor-core fused sparse-conv + LayerNorm + activation, M=32 per warp with
// software-pipelined gathers: the k+1 row gather LDGs are issued before the
// ldsm+mma of tap k, hiding gather latency behind tensor work.
// ---------------------------------------------------------------------------
template <bool RESID>
__global__ void __launch_bounds__(256)
conv_ln_kernel(const __half* __restrict__ in16,    // [N,32] fp16
               const int*    __restrict__ nbr,     // [27,N] native layout
               const float*  __restrict__ W,       // [27,32,32] fp32 (cin-major)
               const float*  __restrict__ gamma,
               const float*  __restrict__ beta,
               const float*  __restrict__ resid,   // fp32 (RESID only)
               __half*       __restrict__ outH,    // !RESID
               float*        __restrict__ outF)    // RESID
{
    extern __shared__ __half smem[];
    __half* wt = smem;                                         // [27*32][40]
    __half* Abuf = smem + SMEM_W_H + (threadIdx.x >> 5) * (A_BYTES / 2);

    // Stage Wt[k][cout][cin] = W[k][cin][cout] as fp16.
    for (int t = threadIdx.x; t < K_TAPS * 1024; t += blockDim.x) {
        const int k = t >> 10, r = t & 1023, cin = r >> 5, cout = r & 31;
        wt[(k * 32 + cout) * W_PITCH_H + cin] = __float2half_rn(W[t]);
    }
    __syncthreads();

    const int lane = threadIdx.x & 31;
    const int rq   = lane >> 2;            // fill row within an 8-row group
    const int seg  = lane & 3;             // 16B segment within a 64B row
    const int qm   = lane & 3;             // quad position (C-frag col pair)

    // A fill STS base (group g adds g*8 rows = g*640 bytes).
    const unsigned sts_base = smem_u32(Abuf) + (unsigned)(rq * A_PITCH_H + seg * 8) * 2;
    // A ldmatrix base: row = lane&15, colblock = (lane>>4)*8; mtile adds 16 rows.
    const unsigned a_base = smem_u32(Abuf) +
        (unsigned)((lane & 15) * A_PITCH_H + (lane >> 4) * 8) * 2;
    // B ldmatrix lane mapping.
    const int bq = lane >> 3, bj = lane & 7;
    const int b_row_off = (bq >> 1) * 8 + bj;
    const int b_koff = (bq & 1) * 8;

    float2 g2[4], bb2[4];
    #pragma unroll
    for (int nt = 0; nt < 4; ++nt) {
        g2[nt]  = *reinterpret_cast<const float2*>(&gamma[nt * 8 + 2 * qm]);
        bb2[nt] = *reinterpret_cast<const float2*>(&beta [nt * 8 + 2 * qm]);
    }

    const int warp_gid   = (blockIdx.x * blockDim.x + threadIdx.x) >> 5;
    const int warp_total = (gridDim.x * blockDim.x) >> 5;

    for (int tile = warp_gid; tile < N_TILES; tile += warp_total) {
        const int i0 = tile * TILE_M;

        float c[2][4][4];
        #pragma unroll
        for (int mt = 0; mt < 2; ++mt)
            #pragma unroll
            for (int nt = 0; nt < 4; ++nt)
                #pragma unroll
                for (int e = 0; e < 4; ++e) c[mt][nt][e] = 0.0f;

        // Prologue: tap 0 indices + gather.
        int idx_cur = nbr[i0 + lane];
        unsigned mask_cur = __ballot_sync(FULL, idx_cur >= 0);
        uint4 v[4];
        #pragma unroll
        for (int g = 0; g < 4; ++g) {
            const int r = __shfl_sync(FULL, idx_cur, g * 8 + rq);
            uint4 t = make_uint4(0u, 0u, 0u, 0u);
            if (r >= 0) t = reinterpret_cast<const uint4*>(in16 + (size_t)r * C)[seg];
            v[g] = t;
        }

        #pragma unroll 1
        for (int k = 0; k < K_TAPS; ++k) {
            int idx_nxt = -1;
            if (k + 1 < K_TAPS) idx_nxt = nbr[(size_t)(k + 1) * N_VOX + i0 + lane];
            const unsigned mask_nxt = __ballot_sync(FULL, idx_nxt >= 0);

            if (mask_cur) {
                // Commit tap k's rows to A (zeros for inactive rows).
                #pragma unroll
                for (int g = 0; g < 4; ++g)
                    asm volatile("st.shared.v4.b32 [%0], {%1,%2,%3,%4};" ::
                                 "r"(sts_base + (unsigned)(g * 8 * A_PITCH_H * 2)),
                                 "r"(v[g].x), "r"(v[g].y), "r"(v[g].z), "r"(v[g].w));
            }

            // Issue tap k+1's gather NOW — latency hidden by ldsm+mma below.
            uint4 vn[4];
            if (mask_nxt) {
                #pragma unroll
                for (int g = 0; g < 4; ++g) {
                    const int r = __shfl_sync(FULL, idx_nxt, g * 8 + rq);
                    uint4 t = make_uint4(0u, 0u, 0u, 0u);
                    if (r >= 0) t = reinterpret_cast<const uint4*>(in16 + (size_t)r * C)[seg];
                    vn[g] = t;
                }
            }

            if (mask_cur) {
                __syncwarp();                       // STS -> ldsm ordering
                const unsigned wbase = smem_u32(wt) + (unsigned)(k * 32) * W_PITCH_H * 2;
                #pragma unroll
                for (int s = 0; s < 2; ++s) {
                    unsigned a0[2][4];
                    #pragma unroll
                    for (int mt = 0; mt < 2; ++mt)
                        ldsm_x4(a_base + (unsigned)((mt * 16 * A_PITCH_H + s * 16) * 2),
                                a0[mt][0], a0[mt][1], a0[mt][2], a0[mt][3]);
                    #pragma unroll
                    for (int p = 0; p < 2; ++p) {
                        const unsigned baddr = wbase +
                            (unsigned)((p * 16 + b_row_off) * W_PITCH_H + s * 16 + b_koff) * 2;
                        unsigned b0, b1, b2, b3;
                        ldsm_x4(baddr, b0, b1, b2, b3);
                        #pragma unroll
                        for (int mt = 0; mt < 2; ++mt) {
                            mma16816(c[mt][2*p  ][0], c[mt][2*p  ][1],
                                     c[mt][2*p  ][2], c[mt][2*p  ][3],
                                     a0[mt][0], a0[mt][1], a0[mt][2], a0[mt][3], b0, b1);
                            mma16816(c[mt][2*p+1][0], c[mt][2*p+1][1],
                                     c[mt][2*p+1][2], c[mt][2*p+1][3],
                                     a0[mt][0], a0[mt][1], a0[mt][2], a0[mt][3], b2, b3);
                        }
                    }
                }
            }

            #pragma unroll
            for (int g = 0; g < 4; ++g) v[g] = vn[g];
            idx_cur = idx_nxt;
            mask_cur = mask_nxt;
        }

        // --- LayerNorm + activation on C fragments (per mtile). ---
        #pragma unroll
        for (int mt = 0; mt < 2; ++mt) {
            float s0 = 0.f, q0 = 0.f, s1 = 0.f, q1 = 0.f;
            #pragma unroll
            for (int nt = 0; nt < 4; ++nt) {
                s0 += c[mt][nt][0] + c[mt][nt][1];
                q0 += c[mt][nt][0] * c[mt][nt][0] + c[mt][nt][1] * c[mt][nt][1];
                s1 += c[mt][nt][2] + c[mt][nt][3];
                q1 += c[mt][nt][2] * c[mt][nt][2] + c[mt][nt][3] * c[mt][nt][3];
            }
            #pragma unroll
            for (int o = 1; o <= 2; o <<= 1) {
                s0 += __shfl_xor_sync(FULL, s0, o);
                q0 += __shfl_xor_sync(FULL, q0, o);
                s1 += __shfl_xor_sync(FULL, s1, o);
                q1 += __shfl_xor_sync(FULL, q1, o);
            }
            const float mu0 = s0 * 0.03125f, var0 = q0 * 0.03125f - mu0 * mu0;
            const float mu1 = s1 * 0.03125f, var1 = q1 * 0.03125f - mu1 * mu1;
            const float rs0 = rsqrtf(var0 + 1e-6f);
            const float rs1 = rsqrtf(var1 + 1e-6f);

            const int row0 = i0 + mt * 16 + rq;
            const int row1 = row0 + 8;
            #pragma unroll
            for (int nt = 0; nt < 4; ++nt) {
                const int colb = nt * 8 + 2 * qm;
                float y00 = (c[mt][nt][0] - mu0) * rs0 * g2[nt].x + bb2[nt].x;
                float y01 = (c[mt][nt][1] - mu0) * rs0 * g2[nt].y + bb2[nt].y;
                float y10 = (c[mt][nt][2] - mu1) * rs1 * g2[nt].x + bb2[nt].x;
                float y11 = (c[mt][nt][3] - mu1) * rs1 * g2[nt].y + bb2[nt].y;
                if (RESID) {
                    const float2 r0v = *reinterpret_cast<const float2*>(&resid[(size_t)row0 * C + colb]);
                    const float2 r1v = *reinterpret_cast<const float2*>(&resid[(size_t)row1 * C + colb]);
                    y00 += r0v.x; y01 += r0v.y; y10 += r1v.x; y11 += r1v.y;
                    *reinterpret_cast<float2*>(&outF[(size_t)row0 * C + colb]) =
                        make_float2(fmaxf(y00, 0.f), fmaxf(y01, 0.f));
                    *reinterpret_cast<float2*>(&outF[(size_t)row1 * C + colb]) =
                        make_float2(fmaxf(y10, 0.f), fmaxf(y11, 0.f));
                } else {
                    *reinterpret_cast<__half2*>(&outH[(size_t)row0 * C + colb]) =
                        __floats2half2_rn(fmaxf(y00, 0.f), fmaxf(y01, 0.f));
                    *reinterpret_cast<__half2*>(&outH[(size_t)row1 * C + colb]) =
                        __floats2half2_rn(fmaxf(y10, 0.f), fmaxf(y11, 0.f));
                }
            }
        }
    }
}

extern "C" void kernel_launch(void* const* d_in, const int* in_sizes, int n_in,
                              void* d_out, int out_size)
{
    const float* x   = (const float*)d_in[0];  // [N, 32]
    const int*   nbr = (const int*)  d_in[1];  // [27, N]
    const float* W1  = (const float*)d_in[2];  // [27, 32, 32]
    const float* g1  = (const float*)d_in[3];
    const float* b1  = (const float*)d_in[4];
    const float* W2  = (const float*)d_in[5];
    const float* g2  = (const float*)d_in[6];
    const float* b2  = (const float*)d_in[7];
    float* out = (float*)d_out;

    __half* x16 = nullptr;
    __half* h16 = nullptr;
    cudaGetSymbolAddress((void**)&x16, g_x16);
    cudaGetSymbolAddress((void**)&h16, g_h16);

    cudaFuncSetAttribute(conv_ln_kernel<false>,
                         cudaFuncAttributeMaxDynamicSharedMemorySize, SMEM_TOTAL);
    cudaFuncSetAttribute(conv_ln_kernel<true>,
                         cudaFuncAttributeMaxDynamicSharedMemorySize, SMEM_TOTAL);

    // 1) x -> fp16   (8 elems per thread)
    prep_kernel<<<(N_VOX * C / 8) / 256, 256>>>(x, x16);

    // 2) Block 1: h16 = relu(LN(conv(x16, W1)))
    conv_ln_kernel<false><<<296, 256, SMEM_TOTAL>>>(x16, nbr, W1, g1, b1,
                                                    nullptr, h16, nullptr);
    // 3) Block 2: out = relu(LN(conv(h16, W2)) + x)
    conv_ln_kernel<true ><<<296, 256, SMEM_TOTAL>>>(h16, nbr, W2, g2, b2,
                                                    x, nullptr, out);
}

// round 17
// speedup vs baseline: 3.9201x; 1.8224x over previous
#include <cuda_runtime.h>
#include <cuda_fp16.h>

#define N_VOX 400000
#define C 32
#define K_TAPS 27
#define FULL 0xffffffffu

#define TILE_M 32
#define N_TILES (N_VOX / TILE_M)              // 12500 exactly

// Wt smem: fp16, row per (k,cout), pitch 40 halfs = 80B (16B-aligned, rows
// walk all 8 bank granules -> conflict-free ldmatrix). Proven R4-R15.
#define W_PITCH_H 40
#define SMEM_W_H (K_TAPS * 32 * W_PITCH_H)    // 34560 halfs
#define SMEM_TOTAL (SMEM_W_H * 2)             // 69,120 B -> 3 CTAs/SM

// Static device scratch (no allocations allowed).
// Both buffers hold PERMUTED rows: within each 32-half row, uint4 slot q holds
// half2s {q, q+4, q+8, q+12} of the logical row — i.e. exactly the
// m16n8k16 A-fragment data for quad-lane q, both k-steps.
__device__ __half g_x16[(size_t)N_VOX * C];   // x (permuted fp16)
__device__ __half g_h16[(size_t)N_VOX * C];   // conv1 output (permuted fp16)

static __device__ __forceinline__ unsigned smem_u32(const void* p) {
    return (unsigned)__cvta_generic_to_shared(p);
}
static __device__ __forceinline__ void ldsm_x4(unsigned addr, unsigned& r0,
                                               unsigned& r1, unsigned& r2, unsigned& r3) {
    asm volatile("ldmatrix.sync.aligned.m8n8.x4.shared.b16 {%0,%1,%2,%3}, [%4];"
                 : "=r"(r0), "=r"(r1), "=r"(r2), "=r"(r3) : "r"(addr));
}
static __device__ __forceinline__ void mma16816(float& d0, float& d1, float& d2, float& d3,
                                                unsigned a0, unsigned a1, unsigned a2, unsigned a3,
                                                unsigned b0, unsigned b1) {
    asm volatile("mma.sync.aligned.m16n8k16.row.col.f32.f16.f16.f32 "
                 "{%0,%1,%2,%3}, {%4,%5,%6,%7}, {%8,%9}, {%0,%1,%2,%3};"
                 : "+f"(d0), "+f"(d1), "+f"(d2), "+f"(d3)
                 : "r"(a0), "r"(a1), "r"(a2), "r"(a3), "r"(b0), "r"(b1));
}

// ---------------------------------------------------------------------------
// Prep: x fp32 -> fp16 with the 4x4 half2 transpose (fragment permutation).
// 4 threads per row; thread q reads float2 cols {q, q+4, q+8, q+12} (x2),
// writes one 16B chunk. Reads/writes fully coalesced.
// ---------------------------------------------------------------------------
__global__ void __launch_bounds__(256)
prep_kernel(const float* __restrict__ x, __half* __restrict__ x16)
{
    const int t = blockIdx.x * blockDim.x + threadIdx.x;      // 1.6M threads
    const int row = t >> 2, q = t & 3;
    const float2* __restrict__ xr = reinterpret_cast<const float2*>(x + (size_t)row * C);
    const float2 f0 = xr[q], f1 = xr[q + 4], f2 = xr[q + 8], f3 = xr[q + 12];
    __half2 h0 = __floats2half2_rn(f0.x, f0.y);
    __half2 h1 = __floats2half2_rn(f1.x, f1.y);
    __half2 h2 = __floats2half2_rn(f2.x, f2.y);
    __half2 h3 = __floats2half2_rn(f3.x, f3.y);
    uint4 o;
    o.x = *reinterpret_cast<unsigned*>(&h0);
    o.y = *reinterpret_cast<unsigned*>(&h1);
    o.z = *reinterpret_cast<unsigned*>(&h2);
    o.w = *reinterpret_cast<unsigned*>(&h3);
    reinterpret_cast<uint4*>(x16 + (size_t)row * C)[q] = o;
}

// ---------------------------------------------------------------------------
// Tensor-core fused sparse-conv + LN + act, M=32/warp, NO smem A staging:
// permuted-gather LDG.128s land directly as mma A-fragments.
// ---------------------------------------------------------------------------
template <bool RESID>
__global__ void __launch_bounds__(256, 3)
conv_ln_kernel(const __half* __restrict__ in16,    // [N,32] fp16 PERMUTED
               const int*    __restrict__ nbr,     // [27,N] native layout
               const float*  __restrict__ W,       // [27,32,32] fp32 (cin-major)
               const float*  __restrict__ gamma,
               const float*  __restrict__ beta,
               const float*  __restrict__ resid,   // fp32 (RESID only)
               __half*       __restrict__ outH,    // !RESID (permuted)
               float*        __restrict__ outF)    // RESID (standard)
{
    extern __shared__ __half wt[];                 // [27*32][40]

    // Stage Wt[k][cout][cin] = W[k][cin][cout] as fp16.
    for (int t = threadIdx.x; t < K_TAPS * 1024; t += blockDim.x) {
        const int k = t >> 10, r = t & 1023, cin = r >> 5, cout = r & 31;
        wt[(k * 32 + cout) * W_PITCH_H + cin] = __float2half_rn(W[t]);
    }
    __syncthreads();

    const int lane = threadIdx.x & 31;
    const int g    = lane >> 2;            // fragment row group 0..7
    const int t4   = lane & 3;             // quad position

    // B ldmatrix lane mapping (unchanged from R13/R15 — validated).
    const int bq = lane >> 3, bj = lane & 7;
    const int b_row_off = (bq >> 1) * 8 + bj;
    const int b_koff = (bq & 1) * 8;

    float2 g2[4], bb2[4];
    #pragma unroll
    for (int nt = 0; nt < 4; ++nt) {
        g2[nt]  = *reinterpret_cast<const float2*>(&gamma[nt * 8 + 2 * t4]);
        bb2[nt] = *reinterpret_cast<const float2*>(&beta [nt * 8 + 2 * t4]);
    }

    const int warp_gid   = (blockIdx.x * blockDim.x + threadIdx.x) >> 5;
    const int warp_total = (gridDim.x * blockDim.x) >> 5;

    for (int tile = warp_gid; tile < N_TILES; tile += warp_total) {
        const int i0 = tile * TILE_M;

        float c[2][4][4];
        #pragma unroll
        for (int mt = 0; mt < 2; ++mt)
            #pragma unroll
            for (int nt = 0; nt < 4; ++nt)
                #pragma unroll
                for (int e = 0; e < 4; ++e) c[mt][nt][e] = 0.0f;

        int idx_cur = nbr[i0 + lane];                        // tap 0

        #pragma unroll 1
        for (int k = 0; k < K_TAPS; ++k) {
            int idx_nxt = -1;
            if (k + 1 < K_TAPS) idx_nxt = nbr[(size_t)(k + 1) * N_VOX + i0 + lane];
            const unsigned mask = __ballot_sync(FULL, idx_cur >= 0);

            if (mask) {
                // Gather A fragments directly: 2 predicated LDG.128 per mtile.
                uint4 u[2], v[2];
                #pragma unroll
                for (int mt = 0; mt < 2; ++mt) {
                    const int ra = __shfl_sync(FULL, idx_cur, mt * 16 + g);
                    const int rb = __shfl_sync(FULL, idx_cur, mt * 16 + 8 + g);
                    uint4 a = make_uint4(0u, 0u, 0u, 0u);
                    uint4 b = make_uint4(0u, 0u, 0u, 0u);
                    if (ra >= 0)
                        a = reinterpret_cast<const uint4*>(in16 + (size_t)ra * C)[t4];
                    if (rb >= 0)
                        b = reinterpret_cast<const uint4*>(in16 + (size_t)rb * C)[t4];
                    u[mt] = a; v[mt] = b;
                }

                const unsigned wbase = smem_u32(wt) + (unsigned)(k * 32) * W_PITCH_H * 2;
                #pragma unroll
                for (int s = 0; s < 2; ++s) {
                    #pragma unroll
                    for (int p = 0; p < 2; ++p) {
                        const unsigned baddr = wbase +
                            (unsigned)((p * 16 + b_row_off) * W_PITCH_H + s * 16 + b_koff) * 2;
                        unsigned b0, b1, b2, b3;
                        ldsm_x4(baddr, b0, b1, b2, b3);
                        #pragma unroll
                        for (int mt = 0; mt < 2; ++mt) {
                            const unsigned a0 = s ? u[mt].z : u[mt].x;
                            const unsigned a1 = s ? v[mt].z : v[mt].x;
                            const unsigned a2 = s ? u[mt].w : u[mt].y;
                            const unsigned a3 = s ? v[mt].w : v[mt].y;
                            mma16816(c[mt][2*p  ][0], c[mt][2*p  ][1],
                                     c[mt][2*p  ][2], c[mt][2*p  ][3],
                                     a0, a1, a2, a3, b0, b1);
                            mma16816(c[mt][2*p+1][0], c[mt][2*p+1][1],
                                     c[mt][2*p+1][2], c[mt][2*p+1][3],
                                     a0, a1, a2, a3, b2, b3);
                        }
                    }
                }
            }
            idx_cur = idx_nxt;
        }

        // --- LayerNorm + activation on C fragments (per mtile). ---
        #pragma unroll
        for (int mt = 0; mt < 2; ++mt) {
            float s0 = 0.f, q0 = 0.f, s1 = 0.f, q1 = 0.f;
            #pragma unroll
            for (int nt = 0; nt < 4; ++nt) {
                s0 += c[mt][nt][0] + c[mt][nt][1];
                q0 += c[mt][nt][0] * c[mt][nt][0] + c[mt][nt][1] * c[mt][nt][1];
                s1 += c[mt][nt][2] + c[mt][nt][3];
                q1 += c[mt][nt][2] * c[mt][nt][2] + c[mt][nt][3] * c[mt][nt][3];
            }
            #pragma unroll
            for (int o = 1; o <= 2; o <<= 1) {
                s0 += __shfl_xor_sync(FULL, s0, o);
                q0 += __shfl_xor_sync(FULL, q0, o);
                s1 += __shfl_xor_sync(FULL, s1, o);
                q1 += __shfl_xor_sync(FULL, q1, o);
            }
            const float mu0 = s0 * 0.03125f, var0 = q0 * 0.03125f - mu0 * mu0;
            const float mu1 = s1 * 0.03125f, var1 = q1 * 0.03125f - mu1 * mu1;
            const float rs0 = rsqrtf(var0 + 1e-6f);
            const float rs1 = rsqrtf(var1 + 1e-6f);

            const int row0 = i0 + mt * 16 + g;
            const int row1 = row0 + 8;

            if (RESID) {
                #pragma unroll
                for (int nt = 0; nt < 4; ++nt) {
                    const int colb = nt * 8 + 2 * t4;
                    float y00 = (c[mt][nt][0] - mu0) * rs0 * g2[nt].x + bb2[nt].x;
                    float y01 = (c[mt][nt][1] - mu0) * rs0 * g2[nt].y + bb2[nt].y;
                    float y10 = (c[mt][nt][2] - mu1) * rs1 * g2[nt].x + bb2[nt].x;
                    float y11 = (c[mt][nt][3] - mu1) * rs1 * g2[nt].y + bb2[nt].y;
                    const float2 r0v = *reinterpret_cast<const float2*>(&resid[(size_t)row0 * C + colb]);
                    const float2 r1v = *reinterpret_cast<const float2*>(&resid[(size_t)row1 * C + colb]);
                    y00 += r0v.x; y01 += r0v.y; y10 += r1v.x; y11 += r1v.y;
                    *reinterpret_cast<float2*>(&outF[(size_t)row0 * C + colb]) =
                        make_float2(fmaxf(y00, 0.f), fmaxf(y01, 0.f));
                    *reinterpret_cast<float2*>(&outF[(size_t)row1 * C + colb]) =
                        make_float2(fmaxf(y10, 0.f), fmaxf(y11, 0.f));
                }
            } else {
                // Permuted fp16 store: thread's 4 half2s (nt=0..3) are exactly
                // uint4 slot t4 of the permuted row -> one STG.128 per row.
                uint4 o0, o1;
                unsigned* o0u = &o0.x;
                unsigned* o1u = &o1.x;
                #pragma unroll
                for (int nt = 0; nt < 4; ++nt) {
                    float y00 = (c[mt][nt][0] - mu0) * rs0 * g2[nt].x + bb2[nt].x;
                    float y01 = (c[mt][nt][1] - mu0) * rs0 * g2[nt].y + bb2[nt].y;
                    float y10 = (c[mt][nt][2] - mu1) * rs1 * g2[nt].x + bb2[nt].x;
                    float y11 = (c[mt][nt][3] - mu1) * rs1 * g2[nt].y + bb2[nt].y;
                    __half2 h0 = __floats2half2_rn(fmaxf(y00, 0.f), fmaxf(y01, 0.f));
                    __half2 h1 = __floats2half2_rn(fmaxf(y10, 0.f), fmaxf(y11, 0.f));
                    o0u[nt] = *reinterpret_cast<unsigned*>(&h0);
                    o1u[nt] = *reinterpret_cast<unsigned*>(&h1);
                }
                reinterpret_cast<uint4*>(outH + (size_t)row0 * C)[t4] = o0;
                reinterpret_cast<uint4*>(outH + (size_t)row1 * C)[t4] = o1;
            }
        }
    }
}

extern "C" void kernel_launch(void* const* d_in, const int* in_sizes, int n_in,
                              void* d_out, int out_size)
{
    const float* x   = (const float*)d_in[0];  // [N, 32]
    const int*   nbr = (const int*)  d_in[1];  // [27, N]
    const float* W1  = (const float*)d_in[2];  // [27, 32, 32]
    const float* g1  = (const float*)d_in[3];
    const float* b1  = (const float*)d_in[4];
    const float* W2  = (const float*)d_in[5];
    const float* g2  = (const float*)d_in[6];
    const float* b2  = (const float*)d_in[7];
    float* out = (float*)d_out;

    __half* x16 = nullptr;
    __half* h16 = nullptr;
    cudaGetSymbolAddress((void**)&x16, g_x16);
    cudaGetSymbolAddress((void**)&h16, g_h16);

    cudaFuncSetAttribute(conv_ln_kernel<false>,
                         cudaFuncAttributeMaxDynamicSharedMemorySize, SMEM_TOTAL);
    cudaFuncSetAttribute(conv_ln_kernel<true>,
                         cudaFuncAttributeMaxDynamicSharedMemorySize, SMEM_TOTAL);

    // 1) x -> fp16, fragment-permuted (4 threads per row).
    prep_kernel<<<(N_VOX * 4) / 256, 256>>>(x, x16);

    // 2) Block 1: h16 = relu(LN(conv(x16, W1)))   (permuted fp16 out)
    conv_ln_kernel<false><<<444, 256, SMEM_TOTAL>>>(x16, nbr, W1, g1, b1,
                                                    nullptr, h16, nullptr);
    // 3) Block 2: out = relu(LN(conv(h16, W2)) + x)   (fp32 standard out)
    conv_ln_kernel<true ><<<444, 256, SMEM_TOTAL>>>(h16, nbr, W2, g2, b2,
                                                    x, nullptr, out);
}